// round 4
// baseline (speedup 1.0000x reference)
#include <cuda_runtime.h>

#define BS     4096
#define SEGLEN 8192
#define LAM1   8e-05f
#define LAM2   8e-05f
#define TPB    256
#define NWARP  (TPB / 32)

// Scratch (allocation-free rule: __device__ globals)
__device__ float        g_base[BS];  // LAM1*smooth + LAM2*spars per row
__device__ int          g_ms[BS];    // argmax index per row
__device__ unsigned int g_ticket;    // zero-initialized; last block resets it

// ---------------------------------------------------------------------------
// One fused kernel. Each block computes one row's stats; the last block to
// finish (ticket) runs the margin/reduction epilogue with everything hot in L2.
// ---------------------------------------------------------------------------
__global__ __launch_bounds__(TPB) void fused(const float* __restrict__ scores,
                                             const int*   __restrict__ labels,
                                             float*       __restrict__ out) {
    __shared__ int   cnt[SEGLEN];                 // 32 KB; used by last block
    __shared__ float ssum[NWARP], ssq[NWARP], smax[NWARP];
    __shared__ int   sidx[NWARP];
    __shared__ int   wtot[32], woff[NWARP];
    __shared__ float red[NWARP];
    __shared__ int   s_last;

    const int row  = blockIdx.x;
    const float*  rf = scores + (size_t)row * SEGLEN;
    const float4* rp = (const float4*)rf;
    const int t = threadIdx.x, lane = t & 31, w = t >> 5;

    // ---- phase 1: row stats --------------------------------------------
    float sum = 0.f, sq = 0.f, maxv = -1.f;
    int   maxq = 0;  // float4-granularity index of running max

#pragma unroll
    for (int k = 0; k < 8; k++) {
        const int v4 = k * TPB + t;
        float4 x = rp[v4];

        // neighbor element 4*v4+4 == lane (t+1)'s x.x this iteration
        float nxt = __shfl_down_sync(0xFFFFFFFFu, x.x, 1);
        if (lane == 31) {
            int e4 = v4 * 4 + 4;
            nxt = (e4 < SEGLEN) ? __ldg(rf + e4) : x.w;  // last elem: diff 0
        }

        sum += (x.x + x.y) + (x.z + x.w);
        float d0 = x.y - x.x, d1 = x.z - x.y, d2 = x.w - x.z, d3 = nxt - x.w;
        sq += d0 * d0 + d1 * d1 + d2 * d2 + d3 * d3;

        // float4-granularity argmax: strict > keeps earliest v4 per thread
        float m4 = fmaxf(fmaxf(x.x, x.y), fmaxf(x.z, x.w));
        if (m4 > maxv) { maxv = m4; maxq = v4; }
    }

    // warp reduce (fixed order -> deterministic); tie -> min v4 index
#pragma unroll
    for (int off = 16; off > 0; off >>= 1) {
        sum += __shfl_down_sync(0xFFFFFFFFu, sum, off);
        sq  += __shfl_down_sync(0xFFFFFFFFu, sq,  off);
        float ov = __shfl_down_sync(0xFFFFFFFFu, maxv, off);
        int   oq = __shfl_down_sync(0xFFFFFFFFu, maxq, off);
        if (ov > maxv || (ov == maxv && oq < maxq)) { maxv = ov; maxq = oq; }
    }
    if (lane == 0) { ssum[w] = sum; ssq[w] = sq; smax[w] = maxv; sidx[w] = maxq; }
    __syncthreads();

    if (t == 0) {
        float S = 0.f, Q = 0.f, M = -1.f;
        int Qi = 0;
#pragma unroll
        for (int i = 0; i < NWARP; i++) {
            S += ssum[i];
            Q += ssq[i];
            if (smax[i] > M || (smax[i] == M && sidx[i] < Qi)) { M = smax[i]; Qi = sidx[i]; }
        }
        // resolve first-occurrence element inside the earliest winning float4
        float4 xx = rp[Qi];
        int e = Qi * 4;
        int idx = (xx.x == M) ? e : (xx.y == M) ? e + 1 : (xx.z == M) ? e + 2 : e + 3;
        g_base[row] = LAM1 * Q + LAM2 * S;
        g_ms[row]   = idx;

        __threadfence();  // publish g_base/g_ms before taking a ticket
        unsigned int v = atomicAdd(&g_ticket, 1u);
        s_last = (v == (unsigned int)(gridDim.x - 1));
    }
    __syncthreads();
    if (!s_last) return;

    // ---- phase 2: last block runs the epilogue --------------------------
    __threadfence();  // acquire: see all blocks' g_base/g_ms

    // zero histogram
#pragma unroll
    for (int i = 0; i < SEGLEN / 4 / TPB; i++)
        ((int4*)cnt)[i * TPB + t] = make_int4(0, 0, 0, 0);
    __syncthreads();

    // histogram of argmax indices over negative rows (smem atomics, int -> det.)
#pragma unroll
    for (int it = 0; it < BS / TPB; it++) {
        int i = it * TPB + t;
        if (labels[i] == 0) atomicAdd(&cnt[g_ms[i]], 1);
    }
    __syncthreads();

    // margin[i] = T[ms[i]] where T = double suffix-sum of the histogram
    const int base = t * 32;  // 32 bins per thread
#pragma unroll
    for (int round = 0; round < 2; round++) {
        int c = 0;
#pragma unroll
        for (int k = 0; k < 32; k++) c += cnt[base + k];

        // warp inclusive suffix scan of per-thread chunk totals
        int incl = c;
#pragma unroll
        for (int off = 1; off < 32; off <<= 1) {
            int v = __shfl_down_sync(0xFFFFFFFFu, incl, off);
            if (lane + off < 32) incl += v;
        }
        if (lane == 0) wtot[w] = incl;
        __syncthreads();

        // warp 0: exclusive suffix over NWARP warp totals (lanes >= NWARP -> 0)
        if (w == 0) {
            int v = (lane < NWARP) ? wtot[lane] : 0;
            int s = v;
#pragma unroll
            for (int off = 1; off < NWARP; off <<= 1) {
                int u = __shfl_down_sync(0xFFFFFFFFu, s, off);
                if (lane + off < 32) s += u;
            }
            if (lane < NWARP) woff[lane] = s - v;
        }
        __syncthreads();

        int r = (incl - c) + woff[w];
#pragma unroll
        for (int k = 31; k >= 0; k--) {
            r += cnt[base + k];
            cnt[base + k] = r;
        }
        __syncthreads();
    }

    // per-positive-row loss, accumulated in fixed order
    float acc = 0.f;
#pragma unroll
    for (int it = 0; it < BS / TPB; it++) {
        int i = it * TPB + t;
        if (labels[i] == 1)
            acc += g_base[i] + (float)cnt[g_ms[i]];
    }

#pragma unroll
    for (int off = 16; off > 0; off >>= 1)
        acc += __shfl_down_sync(0xFFFFFFFFu, acc, off);
    if (lane == 0) red[w] = acc;
    __syncthreads();
    if (t == 0) {
        float v = 0.f;
#pragma unroll
        for (int i = 0; i < NWARP; i++) v += red[i];
        out[0] = v / (float)BS;
        g_ticket = 0;  // reset for next graph replay
    }
}

extern "C" void kernel_launch(void* const* d_in, const int* in_sizes, int n_in,
                              void* d_out, int out_size) {
    const float* scores = (const float*)d_in[0];
    const int*   labels = (const int*)d_in[1];
    float*       out    = (float*)d_out;

    fused<<<BS, TPB>>>(scores, labels, out);
}

// round 5
// speedup vs baseline: 1.1562x; 1.1562x over previous
#include <cuda_runtime.h>

#define BS     4096
#define SEGLEN 8192
#define LAM1   8e-05f
#define LAM2   8e-05f
#define TPB    256
#define NWARP  (TPB / 32)

// Scratch (allocation-free rule: __device__ globals).
// g_hist and g_ticket are zero at load; the epilogue re-zeros them after use
// so every graph replay sees the same initial state.
__device__ float        g_base[BS];     // LAM1*smooth + LAM2*spars per row
__device__ int          g_ms[BS];       // argmax index per row
__device__ int          g_hist[SEGLEN]; // histogram -> T (in place), then re-zeroed
__device__ unsigned int g_ticket;

// ---------------------------------------------------------------------------
// One fused kernel, tiny smem. Each block computes one row's stats; the last
// block (ticket) runs the margin/reduction epilogue on GLOBAL memory (L2-hot).
// ---------------------------------------------------------------------------
__global__ __launch_bounds__(TPB) void fused(const float* __restrict__ scores,
                                             const int*   __restrict__ labels,
                                             float*       __restrict__ out) {
    __shared__ float ssum[NWARP], ssq[NWARP], smax[NWARP];
    __shared__ int   sidx[NWARP];
    __shared__ int   wtot[NWARP], woff[NWARP];
    __shared__ float red[NWARP];
    __shared__ int   s_last;

    const int row  = blockIdx.x;
    const float*  rf = scores + (size_t)row * SEGLEN;
    const float4* rp = (const float4*)rf;
    const int t = threadIdx.x, lane = t & 31, w = t >> 5;

    // ---- phase 1: row stats --------------------------------------------
    float sum = 0.f, sq = 0.f, maxv = -1.f;
    int   maxq = 0;  // float4-granularity index of running max

#pragma unroll
    for (int k = 0; k < 8; k++) {
        const int v4 = k * TPB + t;
        float4 x = rp[v4];

        // neighbor element 4*v4+4 == lane (t+1)'s x.x this iteration
        float nxt = __shfl_down_sync(0xFFFFFFFFu, x.x, 1);
        if (lane == 31) {
            int e4 = v4 * 4 + 4;
            nxt = (e4 < SEGLEN) ? __ldg(rf + e4) : x.w;  // last elem: diff 0
        }

        sum += (x.x + x.y) + (x.z + x.w);
        float d0 = x.y - x.x, d1 = x.z - x.y, d2 = x.w - x.z, d3 = nxt - x.w;
        sq += d0 * d0 + d1 * d1 + d2 * d2 + d3 * d3;

        // float4-granularity argmax: strict > keeps earliest v4 per thread
        float m4 = fmaxf(fmaxf(x.x, x.y), fmaxf(x.z, x.w));
        if (m4 > maxv) { maxv = m4; maxq = v4; }
    }

    // warp reduce (fixed order -> deterministic); tie -> min v4 index
#pragma unroll
    for (int off = 16; off > 0; off >>= 1) {
        sum += __shfl_down_sync(0xFFFFFFFFu, sum, off);
        sq  += __shfl_down_sync(0xFFFFFFFFu, sq,  off);
        float ov = __shfl_down_sync(0xFFFFFFFFu, maxv, off);
        int   oq = __shfl_down_sync(0xFFFFFFFFu, maxq, off);
        if (ov > maxv || (ov == maxv && oq < maxq)) { maxv = ov; maxq = oq; }
    }
    if (lane == 0) { ssum[w] = sum; ssq[w] = sq; smax[w] = maxv; sidx[w] = maxq; }
    __syncthreads();

    if (t == 0) {
        float S = 0.f, Q = 0.f, M = -1.f;
        int Qi = 0;
#pragma unroll
        for (int i = 0; i < NWARP; i++) {
            S += ssum[i];
            Q += ssq[i];
            if (smax[i] > M || (smax[i] == M && sidx[i] < Qi)) { M = smax[i]; Qi = sidx[i]; }
        }
        // resolve first-occurrence element inside the earliest winning float4
        float4 xx = rp[Qi];
        int e = Qi * 4;
        int idx = (xx.x == M) ? e : (xx.y == M) ? e + 1 : (xx.z == M) ? e + 2 : e + 3;
        g_base[row] = LAM1 * Q + LAM2 * S;
        g_ms[row]   = idx;

        __threadfence();  // publish g_base/g_ms before taking a ticket
        unsigned int v = atomicAdd(&g_ticket, 1u);
        s_last = (v == (unsigned int)(gridDim.x - 1));
    }
    __syncthreads();
    if (!s_last) return;

    // ---- phase 2: last block runs the epilogue (global memory, L2-hot) --
    __threadfence();  // acquire: see all blocks' g_base/g_ms

    // histogram of argmax indices over negative rows (g_hist is zero here)
#pragma unroll
    for (int it = 0; it < BS / TPB; it++) {
        int i = it * TPB + t;
        if (labels[i] == 0) atomicAdd(&g_hist[g_ms[i]], 1);
    }
    __syncthreads();  // block-scope visibility of atomics

    // two rounds of suffix-sum over 8192 bins, in place on g_hist.
    // Thread t owns int4 slots [8t, 8t+8) == bins [32t, 32t+32).
    int4* hp = (int4*)g_hist;
#pragma unroll
    for (int round = 0; round < 2; round++) {
        int c = 0;
#pragma unroll
        for (int g = 0; g < 8; g++) {
            int4 v = hp[t * 8 + g];
            c += (v.x + v.y) + (v.z + v.w);
        }

        // warp inclusive suffix scan of per-thread chunk totals
        int incl = c;
#pragma unroll
        for (int off = 1; off < 32; off <<= 1) {
            int v = __shfl_down_sync(0xFFFFFFFFu, incl, off);
            if (lane + off < 32) incl += v;
        }
        if (lane == 0) wtot[w] = incl;
        __syncthreads();

        // warp 0: exclusive suffix over NWARP warp totals
        if (w == 0 && lane < NWARP) {
            int s = 0;
#pragma unroll
            for (int i = 0; i < NWARP; i++)
                if (i > lane) s += wtot[i];
            woff[lane] = s;
        }
        __syncthreads();

        // exclusive suffix of everything strictly after this thread's chunk
        int r = (incl - c) + woff[w];
#pragma unroll
        for (int g = 7; g >= 0; g--) {
            int4 v = hp[t * 8 + g];
            int sw = r + v.w;
            int sz = sw + v.z;
            int sy = sz + v.y;
            int sx = sy + v.x;
            hp[t * 8 + g] = make_int4(sx, sy, sz, sw);
            r = sx;
        }
        __syncthreads();
    }

    // per-positive-row loss, accumulated in fixed order
    float acc = 0.f;
#pragma unroll
    for (int it = 0; it < BS / TPB; it++) {
        int i = it * TPB + t;
        if (labels[i] == 1)
            acc += g_base[i] + (float)g_hist[g_ms[i]];
    }
    __syncthreads();  // all lookups done before re-zeroing

    // self-clean for the next graph replay
#pragma unroll
    for (int g = 0; g < 8; g++)
        hp[t * 8 + g] = make_int4(0, 0, 0, 0);

    // deterministic reduction
#pragma unroll
    for (int off = 16; off > 0; off >>= 1)
        acc += __shfl_down_sync(0xFFFFFFFFu, acc, off);
    if (lane == 0) red[w] = acc;
    __syncthreads();
    if (t == 0) {
        float v = 0.f;
#pragma unroll
        for (int i = 0; i < NWARP; i++) v += red[i];
        out[0] = v / (float)BS;
        g_ticket = 0;  // reset for next replay
    }
}

extern "C" void kernel_launch(void* const* d_in, const int* in_sizes, int n_in,
                              void* d_out, int out_size) {
    const float* scores = (const float*)d_in[0];
    const int*   labels = (const int*)d_in[1];
    float*       out    = (float*)d_out;

    fused<<<BS, TPB>>>(scores, labels, out);
}

// round 6
// speedup vs baseline: 1.4462x; 1.2509x over previous
#include <cuda_runtime.h>

#define BS     4096
#define SEGLEN 8192
#define LAM1   8e-05f
#define LAM2   8e-05f
#define TPB    256
#define NWARP  (TPB / 32)

// Scratch (allocation-free rule: __device__ globals)
__device__ float g_base[BS];  // LAM1*smooth + LAM2*spars per row
__device__ int   g_ms[BS];    // argmax index per row

// ---------------------------------------------------------------------------
// Kernel 1: per-row sum, sum of squared adjacent diffs, first-occurrence
// argmax. One block per row. Each thread owns 32 CONTIGUOUS elements
// (8 front-batched LDG.128, one 128B line per lane -> MLP_p1=8, 7/8 L1 hits).
// Only one boundary shuffle per thread.
// ---------------------------------------------------------------------------
__global__ __launch_bounds__(TPB) void row_stats(const float* __restrict__ scores) {
    const int row = blockIdx.x;
    const float*  rf = scores + (size_t)row * SEGLEN;
    const float4* rp = (const float4*)rf;
    const int t = threadIdx.x, lane = t & 31, w = t >> 5;
    const int base4 = t * 8;       // first float4 index of this thread's chunk
    const int baseE = t * 32;      // first element index

    // front-batched, independent loads (no syncs between them)
    float4 x[8];
#pragma unroll
    for (int g = 0; g < 8; g++) x[g] = rp[base4 + g];

    // boundary element = first element of thread t+1's chunk
    float nxt = __shfl_down_sync(0xFFFFFFFFu, x[0].x, 1);
    if (lane == 31) {
        int e = baseE + 32;
        nxt = (e < SEGLEN) ? __ldg(rf + e) : x[7].w;  // global last elem: diff 0
    }

    float sum = 0.f, sq = 0.f, maxv = -1.f;
    int maxi = 0;
#pragma unroll
    for (int g = 0; g < 8; g++) {
        float nx = (g < 7) ? x[g + 1].x : nxt;
        sum += (x[g].x + x[g].y) + (x[g].z + x[g].w);
        float d0 = x[g].y - x[g].x, d1 = x[g].z - x[g].y;
        float d2 = x[g].w - x[g].z, d3 = nx - x[g].w;
        sq += d0 * d0 + d1 * d1 + d2 * d2 + d3 * d3;

        const int e = baseE + g * 4;
        // strict > keeps first occurrence (indices ascend within thread)
        if (x[g].x > maxv) { maxv = x[g].x; maxi = e;     }
        if (x[g].y > maxv) { maxv = x[g].y; maxi = e + 1; }
        if (x[g].z > maxv) { maxv = x[g].z; maxi = e + 2; }
        if (x[g].w > maxv) { maxv = x[g].w; maxi = e + 3; }
    }

    // warp reduce (fixed order -> deterministic); tie -> min element index
#pragma unroll
    for (int off = 16; off > 0; off >>= 1) {
        sum += __shfl_down_sync(0xFFFFFFFFu, sum, off);
        sq  += __shfl_down_sync(0xFFFFFFFFu, sq,  off);
        float ov = __shfl_down_sync(0xFFFFFFFFu, maxv, off);
        int   oi = __shfl_down_sync(0xFFFFFFFFu, maxi, off);
        if (ov > maxv || (ov == maxv && oi < maxi)) { maxv = ov; maxi = oi; }
    }

    __shared__ float ssum[NWARP], ssq[NWARP], smax[NWARP];
    __shared__ int   sidx[NWARP];
    if (lane == 0) { ssum[w] = sum; ssq[w] = sq; smax[w] = maxv; sidx[w] = maxi; }
    __syncthreads();

    if (t == 0) {
        float S = 0.f, Q = 0.f, M = -1.f;
        int I = 0;
#pragma unroll
        for (int i = 0; i < NWARP; i++) {
            S += ssum[i];
            Q += ssq[i];
            if (smax[i] > M || (smax[i] == M && sidx[i] < I)) { M = smax[i]; I = sidx[i]; }
        }
        g_base[row] = LAM1 * Q + LAM2 * S;
        g_ms[row]   = I;
    }
}

// ---------------------------------------------------------------------------
// Kernel 2 (single block, 1024 threads): prefetch everything into registers
// up front (MLP=3 vector loads/thread), then histogram (smem atomics),
// double suffix-sum (2-level warp-shuffle scans), deterministic reduction.
// ---------------------------------------------------------------------------
__global__ __launch_bounds__(1024) void finalize(const int* __restrict__ labels,
                                                 float* __restrict__ out) {
    __shared__ int   cnt[SEGLEN];   // histogram -> T (in place)
    __shared__ int   wtot[32], woff[32];
    __shared__ float red[32];

    const int t = threadIdx.x;
    const int lane = t & 31, w = t >> 5;
    const int base = t * 8;         // this thread owns bins [8t, 8t+8)

    // front-batched prefetch: rows 4t..4t+3
    int4   ms = ((const int4*)g_ms)[t];
    int4   lb = ((const int4*)labels)[t];
    float4 gb = ((const float4*)g_base)[t];

#pragma unroll
    for (int k = 0; k < 2; k++)
        ((int4*)cnt)[k * 1024 + t] = make_int4(0, 0, 0, 0);
    __syncthreads();

    // histogram of argmax indices over negative rows (int atomics -> det.)
    if (lb.x == 0) atomicAdd(&cnt[ms.x], 1);
    if (lb.y == 0) atomicAdd(&cnt[ms.y], 1);
    if (lb.z == 0) atomicAdd(&cnt[ms.z], 1);
    if (lb.w == 0) atomicAdd(&cnt[ms.w], 1);
    __syncthreads();

    // two rounds of suffix-sum over 8192 bins
#pragma unroll
    for (int round = 0; round < 2; round++) {
        int c = 0;
#pragma unroll
        for (int k = 0; k < 8; k++) c += cnt[base + k];

        // warp inclusive suffix scan of chunk totals
        int incl = c;
#pragma unroll
        for (int off = 1; off < 32; off <<= 1) {
            int v = __shfl_down_sync(0xFFFFFFFFu, incl, off);
            if (lane + off < 32) incl += v;
        }
        if (lane == 0) wtot[w] = incl;
        __syncthreads();

        // warp 0: exclusive suffix scan over 32 warp totals
        if (w == 0) {
            int v = wtot[lane];
            int s = v;
#pragma unroll
            for (int off = 1; off < 32; off <<= 1) {
                int u = __shfl_down_sync(0xFFFFFFFFu, s, off);
                if (lane + off < 32) s += u;
            }
            woff[lane] = s - v;  // sum of warps strictly after lane
        }
        __syncthreads();

        int r = (incl - c) + woff[w];
#pragma unroll
        for (int k = 7; k >= 0; k--) {
            r += cnt[base + k];
            cnt[base + k] = r;
        }
        __syncthreads();
    }

    // per-positive-row loss (this thread's 4 rows), fixed order
    float acc = 0.f;
    if (lb.x == 1) acc += gb.x + (float)cnt[ms.x];
    if (lb.y == 1) acc += gb.y + (float)cnt[ms.y];
    if (lb.z == 1) acc += gb.z + (float)cnt[ms.z];
    if (lb.w == 1) acc += gb.w + (float)cnt[ms.w];

    // deterministic tree reduction
#pragma unroll
    for (int off = 16; off > 0; off >>= 1)
        acc += __shfl_down_sync(0xFFFFFFFFu, acc, off);
    if (lane == 0) red[w] = acc;
    __syncthreads();
    if (w == 0) {
        float v = red[lane];
#pragma unroll
        for (int off = 16; off > 0; off >>= 1)
            v += __shfl_down_sync(0xFFFFFFFFu, v, off);
        if (lane == 0) out[0] = v / (float)BS;
    }
}

extern "C" void kernel_launch(void* const* d_in, const int* in_sizes, int n_in,
                              void* d_out, int out_size) {
    const float* scores = (const float*)d_in[0];
    const int*   labels = (const int*)d_in[1];
    float*       out    = (float*)d_out;

    row_stats<<<BS, TPB>>>(scores);
    finalize<<<1, 1024>>>(labels, out);
}

// round 7
// speedup vs baseline: 1.9788x; 1.3683x over previous
#include <cuda_runtime.h>

#define BS     4096
#define SEGLEN 8192
#define LAM1   8e-05f
#define LAM2   8e-05f
#define TPB    256
#define NWARP  (TPB / 32)

// Scratch (allocation-free rule: __device__ globals)
__device__ float g_base[BS];  // LAM1*smooth + LAM2*spars per row
__device__ int   g_ms[BS];    // argmax index per row

// ---------------------------------------------------------------------------
// Kernel 1: per-row stats. One block per row, coalesced float4 loads
// (lane-contiguous: warp covers 512B per LDG -> 4 lines), all 16 loads
// front-batched and independent. Argmax tracked at float4 granularity
// (fmax tree), exact element resolved once by thread 0.
// ---------------------------------------------------------------------------
__global__ __launch_bounds__(TPB) void row_stats(const float* __restrict__ scores) {
    const int row = blockIdx.x;
    const float*  rf = scores + (size_t)row * SEGLEN;
    const float4* rp = (const float4*)rf;
    const int t = threadIdx.x, lane = t & 31, w = t >> 5;

    // front-batched coalesced loads
    float4 x[8];
#pragma unroll
    for (int g = 0; g < 8; g++) x[g] = rp[g * TPB + t];

    // boundary scalars (element 4*v4+4); mostly L1 hits on just-fetched lines
    float nb[8];
#pragma unroll
    for (int g = 0; g < 8; g++) {
        int e = (g * TPB + t) * 4 + 4;
        nb[g] = (e < SEGLEN) ? __ldg(rf + e) : x[g].w;  // global last elem: diff 0
    }

    float sum = 0.f, sq = 0.f, maxv = -1.f;
    int maxq = 0;  // float4-granularity index of running max
#pragma unroll
    for (int g = 0; g < 8; g++) {
        const int v4 = g * TPB + t;
        sum += (x[g].x + x[g].y) + (x[g].z + x[g].w);
        float d0 = x[g].y - x[g].x, d1 = x[g].z - x[g].y;
        float d2 = x[g].w - x[g].z, d3 = nb[g] - x[g].w;
        sq += d0 * d0 + d1 * d1 + d2 * d2 + d3 * d3;

        // strict > keeps earliest v4 within thread (v4 ascends with g)
        float m4 = fmaxf(fmaxf(x[g].x, x[g].y), fmaxf(x[g].z, x[g].w));
        if (m4 > maxv) { maxv = m4; maxq = v4; }
    }

    // warp reduce (fixed order -> deterministic); tie -> min v4 index
#pragma unroll
    for (int off = 16; off > 0; off >>= 1) {
        sum += __shfl_down_sync(0xFFFFFFFFu, sum, off);
        sq  += __shfl_down_sync(0xFFFFFFFFu, sq,  off);
        float ov = __shfl_down_sync(0xFFFFFFFFu, maxv, off);
        int   oq = __shfl_down_sync(0xFFFFFFFFu, maxq, off);
        if (ov > maxv || (ov == maxv && oq < maxq)) { maxv = ov; maxq = oq; }
    }

    __shared__ float ssum[NWARP], ssq[NWARP], smax[NWARP];
    __shared__ int   sidx[NWARP];
    if (lane == 0) { ssum[w] = sum; ssq[w] = sq; smax[w] = maxv; sidx[w] = maxq; }
    __syncthreads();

    if (t == 0) {
        float S = 0.f, Q = 0.f, M = -1.f;
        int Qi = 0;
#pragma unroll
        for (int i = 0; i < NWARP; i++) {
            S += ssum[i];
            Q += ssq[i];
            if (smax[i] > M || (smax[i] == M && sidx[i] < Qi)) { M = smax[i]; Qi = sidx[i]; }
        }
        // resolve first occurrence inside the earliest winning float4 (L2-hot)
        float4 xx = rp[Qi];
        int e = Qi * 4;
        int idx = (xx.x == M) ? e : (xx.y == M) ? e + 1 : (xx.z == M) ? e + 2 : e + 3;
        g_base[row] = LAM1 * Q + LAM2 * S;
        g_ms[row]   = idx;
    }
    __syncthreads();
    // allow the dependent finalize kernel to start its prologue
    cudaTriggerProgrammaticLaunchCompletion();
}

// ---------------------------------------------------------------------------
// Kernel 2 (single block, 1024 threads, PDL): prologue (smem zero + labels
// load) runs concurrently with row_stats' tail; grid-dependency sync gates
// the g_ms/g_base consumption. Histogram -> double suffix-sum -> gather ->
// deterministic reduction.
// ---------------------------------------------------------------------------
__global__ __launch_bounds__(1024) void finalize(const int* __restrict__ labels,
                                                 float* __restrict__ out) {
    __shared__ int   cnt[SEGLEN];   // histogram -> T (in place)
    __shared__ int   wtot[32], woff[32];
    __shared__ float red[32];

    const int t = threadIdx.x;
    const int lane = t & 31, w = t >> 5;
    const int base = t * 8;         // this thread owns bins [8t, 8t+8)

    // ---- prologue: independent of row_stats ----
#pragma unroll
    for (int k = 0; k < 2; k++)
        ((int4*)cnt)[k * 1024 + t] = make_int4(0, 0, 0, 0);
    int4 lb = ((const int4*)labels)[t];   // rows 4t..4t+3
    __syncthreads();

    // ---- wait for row_stats results ----
    cudaGridDependencySynchronize();
    int4   ms = ((const int4*)g_ms)[t];
    float4 gb = ((const float4*)g_base)[t];

    // histogram of argmax indices over negative rows (int atomics -> det.)
    if (lb.x == 0) atomicAdd(&cnt[ms.x], 1);
    if (lb.y == 0) atomicAdd(&cnt[ms.y], 1);
    if (lb.z == 0) atomicAdd(&cnt[ms.z], 1);
    if (lb.w == 0) atomicAdd(&cnt[ms.w], 1);
    __syncthreads();

    // two rounds of suffix-sum over 8192 bins
#pragma unroll
    for (int round = 0; round < 2; round++) {
        int c = 0;
#pragma unroll
        for (int k = 0; k < 8; k++) c += cnt[base + k];

        // warp inclusive suffix scan of chunk totals
        int incl = c;
#pragma unroll
        for (int off = 1; off < 32; off <<= 1) {
            int v = __shfl_down_sync(0xFFFFFFFFu, incl, off);
            if (lane + off < 32) incl += v;
        }
        if (lane == 0) wtot[w] = incl;
        __syncthreads();

        // warp 0: exclusive suffix scan over 32 warp totals
        if (w == 0) {
            int v = wtot[lane];
            int s = v;
#pragma unroll
            for (int off = 1; off < 32; off <<= 1) {
                int u = __shfl_down_sync(0xFFFFFFFFu, s, off);
                if (lane + off < 32) s += u;
            }
            woff[lane] = s - v;  // sum of warps strictly after lane
        }
        __syncthreads();

        int r = (incl - c) + woff[w];
#pragma unroll
        for (int k = 7; k >= 0; k--) {
            r += cnt[base + k];
            cnt[base + k] = r;
        }
        __syncthreads();
    }

    // per-positive-row loss (this thread's 4 rows), fixed order
    float acc = 0.f;
    if (lb.x == 1) acc += gb.x + (float)cnt[ms.x];
    if (lb.y == 1) acc += gb.y + (float)cnt[ms.y];
    if (lb.z == 1) acc += gb.z + (float)cnt[ms.z];
    if (lb.w == 1) acc += gb.w + (float)cnt[ms.w];

    // deterministic tree reduction
#pragma unroll
    for (int off = 16; off > 0; off >>= 1)
        acc += __shfl_down_sync(0xFFFFFFFFu, acc, off);
    if (lane == 0) red[w] = acc;
    __syncthreads();
    if (w == 0) {
        float v = red[lane];
#pragma unroll
        for (int off = 16; off > 0; off >>= 1)
            v += __shfl_down_sync(0xFFFFFFFFu, v, off);
        if (lane == 0) out[0] = v / (float)BS;
    }
}

extern "C" void kernel_launch(void* const* d_in, const int* in_sizes, int n_in,
                              void* d_out, int out_size) {
    const float* scores = (const float*)d_in[0];
    const int*   labels = (const int*)d_in[1];
    float*       out    = (float*)d_out;

    row_stats<<<BS, TPB>>>(scores);

    // finalize with Programmatic Dependent Launch (overlaps its prologue
    // with row_stats' tail; grid-dep-sync gates data consumption)
    cudaLaunchConfig_t cfg = {};
    cfg.gridDim  = dim3(1, 1, 1);
    cfg.blockDim = dim3(1024, 1, 1);
    cfg.dynamicSmemBytes = 0;
    cudaLaunchAttribute attrs[1];
    attrs[0].id = cudaLaunchAttributeProgrammaticStreamSerialization;
    attrs[0].val.programmaticStreamSerializationAllowed = 1;
    cfg.attrs = attrs;
    cfg.numAttrs = 1;
    cudaLaunchKernelEx(&cfg, finalize, labels, out);
}

// round 8
// speedup vs baseline: 1.9808x; 1.0010x over previous
#include <cuda_runtime.h>

#define BS     4096
#define SEGLEN 8192
#define LAM1   8e-05f
#define LAM2   8e-05f
#define TPB    256
#define NWARP  (TPB / 32)

// Scratch (allocation-free rule: __device__ globals)
__device__ float g_base[BS];  // LAM1*smooth + LAM2*spars per row
__device__ int   g_ms[BS];    // argmax index per row

// ---------------------------------------------------------------------------
// Kernel 1: per-row stats. One block per row, coalesced float4 loads,
// ALL loads front-batched; boundary elements derived via shfl AFTER the
// loads are in flight (lane 31 only: predicated __ldg, L1 hit).
// LDG/thread: 8.25 instead of 16 -> LSU issue pressure halved.
// ---------------------------------------------------------------------------
__global__ __launch_bounds__(TPB) void row_stats(const float* __restrict__ scores) {
    const int row = blockIdx.x;
    const float*  rf = scores + (size_t)row * SEGLEN;
    const float4* rp = (const float4*)rf;
    const int t = threadIdx.x, lane = t & 31, w = t >> 5;

    // front-batched coalesced loads (8 independent LDG.128)
    float4 x[8];
#pragma unroll
    for (int g = 0; g < 8; g++) x[g] = rp[g * TPB + t];

    // boundary element for float4 v4 = element 4*v4+4 = x.x of float4 v4+1,
    // which lives in lane t+1 (same g). Cross-warp lane 31 reloads (L1 hit).
    float nb[8];
#pragma unroll
    for (int g = 0; g < 8; g++) {
        nb[g] = __shfl_down_sync(0xFFFFFFFFu, x[g].x, 1);
        if (lane == 31) {
            int e = (g * TPB + t) * 4 + 4;
            nb[g] = (e < SEGLEN) ? __ldg(rf + e) : x[g].w;  // last elem: diff 0
        }
    }

    float sum = 0.f, sq = 0.f, maxv = -1.f;
    int maxq = 0;  // float4-granularity index of running max
#pragma unroll
    for (int g = 0; g < 8; g++) {
        const int v4 = g * TPB + t;
        sum += (x[g].x + x[g].y) + (x[g].z + x[g].w);
        float d0 = x[g].y - x[g].x, d1 = x[g].z - x[g].y;
        float d2 = x[g].w - x[g].z, d3 = nb[g] - x[g].w;
        sq += d0 * d0 + d1 * d1 + d2 * d2 + d3 * d3;

        // strict > keeps earliest v4 within thread (v4 ascends with g)
        float m4 = fmaxf(fmaxf(x[g].x, x[g].y), fmaxf(x[g].z, x[g].w));
        if (m4 > maxv) { maxv = m4; maxq = v4; }
    }

    // warp reduce (fixed order -> deterministic); tie -> min v4 index
#pragma unroll
    for (int off = 16; off > 0; off >>= 1) {
        sum += __shfl_down_sync(0xFFFFFFFFu, sum, off);
        sq  += __shfl_down_sync(0xFFFFFFFFu, sq,  off);
        float ov = __shfl_down_sync(0xFFFFFFFFu, maxv, off);
        int   oq = __shfl_down_sync(0xFFFFFFFFu, maxq, off);
        if (ov > maxv || (ov == maxv && oq < maxq)) { maxv = ov; maxq = oq; }
    }

    __shared__ float ssum[NWARP], ssq[NWARP], smax[NWARP];
    __shared__ int   sidx[NWARP];
    if (lane == 0) { ssum[w] = sum; ssq[w] = sq; smax[w] = maxv; sidx[w] = maxq; }
    __syncthreads();

    if (t == 0) {
        float S = 0.f, Q = 0.f, M = -1.f;
        int Qi = 0;
#pragma unroll
        for (int i = 0; i < NWARP; i++) {
            S += ssum[i];
            Q += ssq[i];
            if (smax[i] > M || (smax[i] == M && sidx[i] < Qi)) { M = smax[i]; Qi = sidx[i]; }
        }
        // resolve first occurrence inside the earliest winning float4 (L2-hot)
        float4 xx = rp[Qi];
        int e = Qi * 4;
        int idx = (xx.x == M) ? e : (xx.y == M) ? e + 1 : (xx.z == M) ? e + 2 : e + 3;
        g_base[row] = LAM1 * Q + LAM2 * S;
        g_ms[row]   = idx;
    }
    __syncthreads();
    // allow the dependent finalize kernel to start its prologue
    cudaTriggerProgrammaticLaunchCompletion();
}

// ---------------------------------------------------------------------------
// Kernel 2 (single block, 1024 threads, PDL): prologue (smem zero + labels
// load) overlaps row_stats' tail; grid-dependency sync gates g_ms/g_base use.
// Histogram -> double suffix-sum -> gather -> deterministic reduction.
// ---------------------------------------------------------------------------
__global__ __launch_bounds__(1024) void finalize(const int* __restrict__ labels,
                                                 float* __restrict__ out) {
    __shared__ int   cnt[SEGLEN];   // histogram -> T (in place)
    __shared__ int   wtot[32], woff[32];
    __shared__ float red[32];

    const int t = threadIdx.x;
    const int lane = t & 31, w = t >> 5;
    const int base = t * 8;         // this thread owns bins [8t, 8t+8)

    // ---- prologue: independent of row_stats ----
#pragma unroll
    for (int k = 0; k < 2; k++)
        ((int4*)cnt)[k * 1024 + t] = make_int4(0, 0, 0, 0);
    int4 lb = ((const int4*)labels)[t];   // rows 4t..4t+3
    __syncthreads();

    // ---- wait for row_stats results ----
    cudaGridDependencySynchronize();
    int4   ms = ((const int4*)g_ms)[t];
    float4 gb = ((const float4*)g_base)[t];

    // histogram of argmax indices over negative rows (int atomics -> det.)
    if (lb.x == 0) atomicAdd(&cnt[ms.x], 1);
    if (lb.y == 0) atomicAdd(&cnt[ms.y], 1);
    if (lb.z == 0) atomicAdd(&cnt[ms.z], 1);
    if (lb.w == 0) atomicAdd(&cnt[ms.w], 1);
    __syncthreads();

    // two rounds of suffix-sum over 8192 bins
#pragma unroll
    for (int round = 0; round < 2; round++) {
        int c = 0;
#pragma unroll
        for (int k = 0; k < 8; k++) c += cnt[base + k];

        // warp inclusive suffix scan of chunk totals
        int incl = c;
#pragma unroll
        for (int off = 1; off < 32; off <<= 1) {
            int v = __shfl_down_sync(0xFFFFFFFFu, incl, off);
            if (lane + off < 32) incl += v;
        }
        if (lane == 0) wtot[w] = incl;
        __syncthreads();

        // warp 0: exclusive suffix scan over 32 warp totals
        if (w == 0) {
            int v = wtot[lane];
            int s = v;
#pragma unroll
            for (int off = 1; off < 32; off <<= 1) {
                int u = __shfl_down_sync(0xFFFFFFFFu, s, off);
                if (lane + off < 32) s += u;
            }
            woff[lane] = s - v;  // sum of warps strictly after lane
        }
        __syncthreads();

        int r = (incl - c) + woff[w];
#pragma unroll
        for (int k = 7; k >= 0; k--) {
            r += cnt[base + k];
            cnt[base + k] = r;
        }
        __syncthreads();
    }

    // per-positive-row loss (this thread's 4 rows), fixed order
    float acc = 0.f;
    if (lb.x == 1) acc += gb.x + (float)cnt[ms.x];
    if (lb.y == 1) acc += gb.y + (float)cnt[ms.y];
    if (lb.z == 1) acc += gb.z + (float)cnt[ms.z];
    if (lb.w == 1) acc += gb.w + (float)cnt[ms.w];

    // deterministic tree reduction
#pragma unroll
    for (int off = 16; off > 0; off >>= 1)
        acc += __shfl_down_sync(0xFFFFFFFFu, acc, off);
    if (lane == 0) red[w] = acc;
    __syncthreads();
    if (w == 0) {
        float v = red[lane];
#pragma unroll
        for (int off = 16; off > 0; off >>= 1)
            v += __shfl_down_sync(0xFFFFFFFFu, v, off);
        if (lane == 0) out[0] = v / (float)BS;
    }
}

extern "C" void kernel_launch(void* const* d_in, const int* in_sizes, int n_in,
                              void* d_out, int out_size) {
    const float* scores = (const float*)d_in[0];
    const int*   labels = (const int*)d_in[1];
    float*       out    = (float*)d_out;

    row_stats<<<BS, TPB>>>(scores);

    // finalize with Programmatic Dependent Launch
    cudaLaunchConfig_t cfg = {};
    cfg.gridDim  = dim3(1, 1, 1);
    cfg.blockDim = dim3(1024, 1, 1);
    cfg.dynamicSmemBytes = 0;
    cudaLaunchAttribute attrs[1];
    attrs[0].id = cudaLaunchAttributeProgrammaticStreamSerialization;
    attrs[0].val.programmaticStreamSerializationAllowed = 1;
    cfg.attrs = attrs;
    cfg.numAttrs = 1;
    cudaLaunchKernelEx(&cfg, finalize, labels, out);
}

// round 9
// speedup vs baseline: 2.0957x; 1.0580x over previous
#include <cuda_runtime.h>

#define BS     4096
#define SEGLEN 8192
#define LAM1   8e-05f
#define LAM2   8e-05f
#define TPB    256
#define NWARP  (TPB / 32)

// Scratch (allocation-free rule: __device__ globals).
// g_hist is zero at load; finalize re-zeros it after use (replay-safe).
__device__ float g_base[BS];     // LAM1*smooth + LAM2*spars per row
__device__ int   g_ms[BS];       // argmax index per row
__device__ int   g_hist[SEGLEN]; // histogram of ms over negative rows

// ---------------------------------------------------------------------------
// Kernel 1: per-row stats + incremental global histogram.
// One block per row, coalesced front-batched float4 loads, boundary via shfl.
// ---------------------------------------------------------------------------
__global__ __launch_bounds__(TPB) void row_stats(const float* __restrict__ scores,
                                                 const int*   __restrict__ labels) {
    const int row = blockIdx.x;
    const float*  rf = scores + (size_t)row * SEGLEN;
    const float4* rp = (const float4*)rf;
    const int t = threadIdx.x, lane = t & 31, w = t >> 5;

    // front-batched coalesced loads (8 independent LDG.128)
    float4 x[8];
#pragma unroll
    for (int g = 0; g < 8; g++) x[g] = rp[g * TPB + t];

    // boundary element for float4 v4 = x.x of float4 v4+1 = lane t+1 (same g)
    float nb[8];
#pragma unroll
    for (int g = 0; g < 8; g++) {
        nb[g] = __shfl_down_sync(0xFFFFFFFFu, x[g].x, 1);
        if (lane == 31) {
            int e = (g * TPB + t) * 4 + 4;
            nb[g] = (e < SEGLEN) ? __ldg(rf + e) : x[g].w;  // last elem: diff 0
        }
    }

    float sum = 0.f, sq = 0.f, maxv = -1.f;
    int maxq = 0;  // float4-granularity index of running max
#pragma unroll
    for (int g = 0; g < 8; g++) {
        const int v4 = g * TPB + t;
        sum += (x[g].x + x[g].y) + (x[g].z + x[g].w);
        float d0 = x[g].y - x[g].x, d1 = x[g].z - x[g].y;
        float d2 = x[g].w - x[g].z, d3 = nb[g] - x[g].w;
        sq += d0 * d0 + d1 * d1 + d2 * d2 + d3 * d3;

        float m4 = fmaxf(fmaxf(x[g].x, x[g].y), fmaxf(x[g].z, x[g].w));
        if (m4 > maxv) { maxv = m4; maxq = v4; }  // strict > keeps earliest v4
    }

    // warp reduce (fixed order -> deterministic); tie -> min v4 index
#pragma unroll
    for (int off = 16; off > 0; off >>= 1) {
        sum += __shfl_down_sync(0xFFFFFFFFu, sum, off);
        sq  += __shfl_down_sync(0xFFFFFFFFu, sq,  off);
        float ov = __shfl_down_sync(0xFFFFFFFFu, maxv, off);
        int   oq = __shfl_down_sync(0xFFFFFFFFu, maxq, off);
        if (ov > maxv || (ov == maxv && oq < maxq)) { maxv = ov; maxq = oq; }
    }

    __shared__ float ssum[NWARP], ssq[NWARP], smax[NWARP];
    __shared__ int   sidx[NWARP];
    if (lane == 0) { ssum[w] = sum; ssq[w] = sq; smax[w] = maxv; sidx[w] = maxq; }
    __syncthreads();

    if (t == 0) {
        float S = 0.f, Q = 0.f, M = -1.f;
        int Qi = 0;
#pragma unroll
        for (int i = 0; i < NWARP; i++) {
            S += ssum[i];
            Q += ssq[i];
            if (smax[i] > M || (smax[i] == M && sidx[i] < Qi)) { M = smax[i]; Qi = sidx[i]; }
        }
        // resolve first occurrence inside the earliest winning float4 (L2-hot)
        float4 xx = rp[Qi];
        int e = Qi * 4;
        int idx = (xx.x == M) ? e : (xx.y == M) ? e + 1 : (xx.z == M) ? e + 2 : e + 3;
        g_base[row] = LAM1 * Q + LAM2 * S;
        g_ms[row]   = idx;
        if (labels[row] == 0) atomicAdd(&g_hist[idx], 1);  // int -> deterministic
    }
    __syncthreads();
    cudaTriggerProgrammaticLaunchCompletion();
}

// ---------------------------------------------------------------------------
// Kernel 2 (single block, 1024 threads, PDL):
//   T[m] = sum_{v>=m} h[v]*(v+1-m) = S1[m] - m*S0[m], computed with ONE fused
//   suffix scan of the pair (S0, S1) written straight into smem. Then gather
//   margin = T[ms[i]] for positive rows + deterministic reduction.
//   Self-cleans g_hist for the next graph replay.
// ---------------------------------------------------------------------------
__global__ __launch_bounds__(1024) void finalize(const int* __restrict__ labels,
                                                 float* __restrict__ out) {
    __shared__ int   Tm[SEGLEN];    // T[m]
    __shared__ int   wt0[32], wt1[32], wo0[32], wo1[32];
    __shared__ float red[32];

    const int t = threadIdx.x;
    const int lane = t & 31, w = t >> 5;
    const int base = t * 8;         // this thread owns bins [8t, 8t+8)

    // ---- prologue: independent of row_stats ----
    int4 lb = ((const int4*)labels)[t];   // rows 4t..4t+3
    // ---- wait for row_stats results ----
    cudaGridDependencySynchronize();

    // load this thread's 8 hist bins (coalesced int4, L2-hot)
    int4 h0 = ((const int4*)g_hist)[2 * t];
    int4 h1 = ((const int4*)g_hist)[2 * t + 1];
    int4   ms = ((const int4*)g_ms)[t];
    float4 gb = ((const float4*)g_base)[t];

    int hreg[8] = {h0.x, h0.y, h0.z, h0.w, h1.x, h1.y, h1.z, h1.w};

    // chunk totals: c0 = sum h, c1 = sum h*(bin+1)
    int c0 = 0, c1 = 0;
#pragma unroll
    for (int k = 0; k < 8; k++) { c0 += hreg[k]; c1 += hreg[k] * (base + k + 1); }

    // warp inclusive suffix scan of (c0, c1)
    int i0 = c0, i1 = c1;
#pragma unroll
    for (int off = 1; off < 32; off <<= 1) {
        int v0 = __shfl_down_sync(0xFFFFFFFFu, i0, off);
        int v1 = __shfl_down_sync(0xFFFFFFFFu, i1, off);
        if (lane + off < 32) { i0 += v0; i1 += v1; }
    }
    if (lane == 0) { wt0[w] = i0; wt1[w] = i1; }
    __syncthreads();

    // warp 0: exclusive suffix over 32 warp totals (both components)
    if (w == 0) {
        int v0 = wt0[lane], v1 = wt1[lane];
        int s0 = v0, s1 = v1;
#pragma unroll
        for (int off = 1; off < 32; off <<= 1) {
            int u0 = __shfl_down_sync(0xFFFFFFFFu, s0, off);
            int u1 = __shfl_down_sync(0xFFFFFFFFu, s1, off);
            if (lane + off < 32) { s0 += u0; s1 += u1; }
        }
        wo0[lane] = s0 - v0;  // sum of warps strictly after lane
        wo1[lane] = s1 - v1;
    }
    __syncthreads();

    // serial descending within chunk: inclusive suffixes r0, r1; write T
    int r0 = (i0 - c0) + wo0[w];
    int r1 = (i1 - c1) + wo1[w];
#pragma unroll
    for (int k = 7; k >= 0; k--) {
        const int bin = base + k;
        r0 += hreg[k];
        r1 += hreg[k] * (bin + 1);
        Tm[bin] = r1 - bin * r0;
    }
    __syncthreads();

    // per-positive-row loss (this thread's 4 rows), fixed order
    float acc = 0.f;
    if (lb.x == 1) acc += gb.x + (float)Tm[ms.x];
    if (lb.y == 1) acc += gb.y + (float)Tm[ms.y];
    if (lb.z == 1) acc += gb.z + (float)Tm[ms.z];
    if (lb.w == 1) acc += gb.w + (float)Tm[ms.w];

    // self-clean histogram for the next graph replay
    ((int4*)g_hist)[2 * t]     = make_int4(0, 0, 0, 0);
    ((int4*)g_hist)[2 * t + 1] = make_int4(0, 0, 0, 0);

    // deterministic tree reduction
#pragma unroll
    for (int off = 16; off > 0; off >>= 1)
        acc += __shfl_down_sync(0xFFFFFFFFu, acc, off);
    if (lane == 0) red[w] = acc;
    __syncthreads();
    if (w == 0) {
        float v = red[lane];
#pragma unroll
        for (int off = 16; off > 0; off >>= 1)
            v += __shfl_down_sync(0xFFFFFFFFu, v, off);
        if (lane == 0) out[0] = v / (float)BS;
    }
}

extern "C" void kernel_launch(void* const* d_in, const int* in_sizes, int n_in,
                              void* d_out, int out_size) {
    const float* scores = (const float*)d_in[0];
    const int*   labels = (const int*)d_in[1];
    float*       out    = (float*)d_out;

    row_stats<<<BS, TPB>>>(scores, labels);

    // finalize with Programmatic Dependent Launch
    cudaLaunchConfig_t cfg = {};
    cfg.gridDim  = dim3(1, 1, 1);
    cfg.blockDim = dim3(1024, 1, 1);
    cfg.dynamicSmemBytes = 0;
    cudaLaunchAttribute attrs[1];
    attrs[0].id = cudaLaunchAttributeProgrammaticStreamSerialization;
    attrs[0].val.programmaticStreamSerializationAllowed = 1;
    cfg.attrs = attrs;
    cfg.numAttrs = 1;
    cudaLaunchKernelEx(&cfg, finalize, labels, out);
}

// round 10
// speedup vs baseline: 2.1108x; 1.0072x over previous
#include <cuda_runtime.h>

#define BS     4096
#define SEGLEN 8192
#define LAM1   8e-05f
#define LAM2   8e-05f
#define TPB    256
#define NWARP  (TPB / 32)

// Scratch (allocation-free rule: __device__ globals).
// g_hist is zero at load; finalize re-zeros it after use (replay-safe).
__device__ float g_base[BS];     // LAM1*smooth + LAM2*spars per row
__device__ int   g_ms[BS];       // argmax index per row
__device__ int   g_hist[SEGLEN]; // histogram of ms over negative rows

// ---------------------------------------------------------------------------
// Kernel 1: per-row stats + incremental global histogram.
// One block per row, interleaved load loop (measured fastest layout: R1),
// float4-granularity argmax, boundary scalar __ldg (L1 hit).
// ---------------------------------------------------------------------------
__global__ __launch_bounds__(TPB) void row_stats(const float* __restrict__ scores,
                                                 const int*   __restrict__ labels) {
    const int row = blockIdx.x;
    const float*  rf = scores + (size_t)row * SEGLEN;
    const float4* rp = (const float4*)rf;
    const int t = threadIdx.x, lane = t & 31, w = t >> 5;

    float sum = 0.f, sq = 0.f, maxv = -1.f;
    int maxq = 0;  // float4-granularity index of running max

#pragma unroll
    for (int g = 0; g < 8; g++) {
        const int v4 = g * TPB + t;     // coalesced across lanes
        const int e  = v4 * 4;
        float4 x = rp[v4];
        float nxt = (e + 4 < SEGLEN) ? __ldg(rf + e + 4) : x.w;  // last elem: diff 0

        sum += (x.x + x.y) + (x.z + x.w);
        float d0 = x.y - x.x, d1 = x.z - x.y, d2 = x.w - x.z, d3 = nxt - x.w;
        sq += d0 * d0 + d1 * d1 + d2 * d2 + d3 * d3;

        // strict > keeps earliest v4 within thread (v4 ascends with g)
        float m4 = fmaxf(fmaxf(x.x, x.y), fmaxf(x.z, x.w));
        if (m4 > maxv) { maxv = m4; maxq = v4; }
    }

    // warp reduce (fixed order -> deterministic); tie -> min v4 index
#pragma unroll
    for (int off = 16; off > 0; off >>= 1) {
        sum += __shfl_down_sync(0xFFFFFFFFu, sum, off);
        sq  += __shfl_down_sync(0xFFFFFFFFu, sq,  off);
        float ov = __shfl_down_sync(0xFFFFFFFFu, maxv, off);
        int   oq = __shfl_down_sync(0xFFFFFFFFu, maxq, off);
        if (ov > maxv || (ov == maxv && oq < maxq)) { maxv = ov; maxq = oq; }
    }

    __shared__ float ssum[NWARP], ssq[NWARP], smax[NWARP];
    __shared__ int   sidx[NWARP];
    if (lane == 0) { ssum[w] = sum; ssq[w] = sq; smax[w] = maxv; sidx[w] = maxq; }
    __syncthreads();

    if (t == 0) {
        float S = 0.f, Q = 0.f, M = -1.f;
        int Qi = 0;
#pragma unroll
        for (int i = 0; i < NWARP; i++) {
            S += ssum[i];
            Q += ssq[i];
            if (smax[i] > M || (smax[i] == M && sidx[i] < Qi)) { M = smax[i]; Qi = sidx[i]; }
        }
        // resolve first occurrence inside the earliest winning float4 (L2-hot)
        float4 xx = rp[Qi];
        int e = Qi * 4;
        int idx = (xx.x == M) ? e : (xx.y == M) ? e + 1 : (xx.z == M) ? e + 2 : e + 3;
        g_base[row] = LAM1 * Q + LAM2 * S;
        g_ms[row]   = idx;
        if (labels[row] == 0) atomicAdd(&g_hist[idx], 1);  // int -> deterministic
    }
    __syncthreads();
    cudaTriggerProgrammaticLaunchCompletion();
}

// ---------------------------------------------------------------------------
// Kernel 2 (single block, 1024 threads, PDL):
//   T[m] = S1[m] - m*S0[m] via one fused suffix scan of (S0, S1).
//   Gather margin = T[ms[i]] for positive rows + deterministic reduction.
//   Self-cleans g_hist for the next graph replay.
// ---------------------------------------------------------------------------
__global__ __launch_bounds__(1024) void finalize(const int* __restrict__ labels,
                                                 float* __restrict__ out) {
    __shared__ int   Tm[SEGLEN];    // T[m]
    __shared__ int   wt0[32], wt1[32], wo0[32], wo1[32];
    __shared__ float red[32];

    const int t = threadIdx.x;
    const int lane = t & 31, w = t >> 5;
    const int base = t * 8;         // this thread owns bins [8t, 8t+8)

    // ---- prologue: independent of row_stats ----
    int4 lb = ((const int4*)labels)[t];   // rows 4t..4t+3
    // ---- wait for row_stats results ----
    cudaGridDependencySynchronize();

    // load this thread's 8 hist bins (coalesced int4, L2-hot)
    int4 h0 = ((const int4*)g_hist)[2 * t];
    int4 h1 = ((const int4*)g_hist)[2 * t + 1];
    int4   ms = ((const int4*)g_ms)[t];
    float4 gb = ((const float4*)g_base)[t];

    int hreg[8] = {h0.x, h0.y, h0.z, h0.w, h1.x, h1.y, h1.z, h1.w};

    // chunk totals: c0 = sum h, c1 = sum h*(bin+1)
    int c0 = 0, c1 = 0;
#pragma unroll
    for (int k = 0; k < 8; k++) { c0 += hreg[k]; c1 += hreg[k] * (base + k + 1); }

    // warp inclusive suffix scan of (c0, c1)
    int i0 = c0, i1 = c1;
#pragma unroll
    for (int off = 1; off < 32; off <<= 1) {
        int v0 = __shfl_down_sync(0xFFFFFFFFu, i0, off);
        int v1 = __shfl_down_sync(0xFFFFFFFFu, i1, off);
        if (lane + off < 32) { i0 += v0; i1 += v1; }
    }
    if (lane == 0) { wt0[w] = i0; wt1[w] = i1; }
    __syncthreads();

    // warp 0: exclusive suffix over 32 warp totals (both components)
    if (w == 0) {
        int v0 = wt0[lane], v1 = wt1[lane];
        int s0 = v0, s1 = v1;
#pragma unroll
        for (int off = 1; off < 32; off <<= 1) {
            int u0 = __shfl_down_sync(0xFFFFFFFFu, s0, off);
            int u1 = __shfl_down_sync(0xFFFFFFFFu, s1, off);
            if (lane + off < 32) { s0 += u0; s1 += u1; }
        }
        wo0[lane] = s0 - v0;  // sum of warps strictly after lane
        wo1[lane] = s1 - v1;
    }
    __syncthreads();

    // serial descending within chunk: inclusive suffixes r0, r1; write T
    int r0 = (i0 - c0) + wo0[w];
    int r1 = (i1 - c1) + wo1[w];
#pragma unroll
    for (int k = 7; k >= 0; k--) {
        const int bin = base + k;
        r0 += hreg[k];
        r1 += hreg[k] * (bin + 1);
        Tm[bin] = r1 - bin * r0;
    }
    __syncthreads();

    // per-positive-row loss (this thread's 4 rows), fixed order
    float acc = 0.f;
    if (lb.x == 1) acc += gb.x + (float)Tm[ms.x];
    if (lb.y == 1) acc += gb.y + (float)Tm[ms.y];
    if (lb.z == 1) acc += gb.z + (float)Tm[ms.z];
    if (lb.w == 1) acc += gb.w + (float)Tm[ms.w];

    // self-clean histogram for the next graph replay
    ((int4*)g_hist)[2 * t]     = make_int4(0, 0, 0, 0);
    ((int4*)g_hist)[2 * t + 1] = make_int4(0, 0, 0, 0);

    // deterministic tree reduction
#pragma unroll
    for (int off = 16; off > 0; off >>= 1)
        acc += __shfl_down_sync(0xFFFFFFFFu, acc, off);
    if (lane == 0) red[w] = acc;
    __syncthreads();
    if (w == 0) {
        float v = red[lane];
#pragma unroll
        for (int off = 16; off > 0; off >>= 1)
            v += __shfl_down_sync(0xFFFFFFFFu, v, off);
        if (lane == 0) out[0] = v / (float)BS;
    }
}

extern "C" void kernel_launch(void* const* d_in, const int* in_sizes, int n_in,
                              void* d_out, int out_size) {
    const float* scores = (const float*)d_in[0];
    const int*   labels = (const int*)d_in[1];
    float*       out    = (float*)d_out;

    row_stats<<<BS, TPB>>>(scores, labels);

    // finalize with Programmatic Dependent Launch
    cudaLaunchConfig_t cfg = {};
    cfg.gridDim  = dim3(1, 1, 1);
    cfg.blockDim = dim3(1024, 1, 1);
    cfg.dynamicSmemBytes = 0;
    cudaLaunchAttribute attrs[1];
    attrs[0].id = cudaLaunchAttributeProgrammaticStreamSerialization;
    attrs[0].val.programmaticStreamSerializationAllowed = 1;
    cfg.attrs = attrs;
    cfg.numAttrs = 1;
    cudaLaunchKernelEx(&cfg, finalize, labels, out);
}